// round 2
// baseline (speedup 1.0000x reference)
#include <cuda_runtime.h>
#include <cuda_bf16.h>

// Problem constants (fixed by reference setup_inputs)
#define BATCH 4096
#define CELL  400
#define KMIX  10      // K gaussian components
#define TLEN  256     // text_len
#define VDIM  80
#define NTHREADS 320  // 10 warps: 4 groups of 80 for the einsum phase

__global__ __launch_bounds__(NTHREADS)
void window_kernel(const float* __restrict__ x,
                   const float* __restrict__ kappa_old,
                   const float* __restrict__ onehots,
                   const float* __restrict__ W,
                   const float* __restrict__ bias,
                   float* __restrict__ out_weight,   // [BATCH, VDIM]
                   float* __restrict__ out_kappa)    // [BATCH, KMIX]
{
    const int b   = blockIdx.x;
    const int tid = threadIdx.x;

    __shared__ float sx[CELL];          // x row
    __shared__ float sparams[32];       // 30 linear outputs
    __shared__ float salpha[KMIX], sbeta[KMIX], skappa[KMIX];
    __shared__ float sphi[TLEN];
    __shared__ float wpart[4 * VDIM];   // per-group partial weights

    // ---- Phase 0: stage x[b] in shared ----
    const float* xb = x + (size_t)b * CELL;
    for (int i = tid; i < CELL; i += NTHREADS) sx[i] = xb[i];
    __syncthreads();

    // ---- Phase 1: params = x[b] @ W^T + bias  (30 outputs) ----
    // warp w handles params w, w+10, w+20 (10 warps)
    const int warp = tid >> 5;
    const int lane = tid & 31;
    for (int p = warp; p < 3 * KMIX; p += 10) {
        const float* wrow = W + (size_t)p * CELL;
        float s = 0.0f;
        for (int c = lane; c < CELL; c += 32) s += sx[c] * wrow[c];
        #pragma unroll
        for (int off = 16; off > 0; off >>= 1)
            s += __shfl_down_sync(0xffffffffu, s, off);
        if (lane == 0) sparams[p] = s + bias[p];
    }
    __syncthreads();

    // ---- Phase 2: alpha/beta/kappa; write kappa out ----
    if (tid < KMIX) {
        float kap = kappa_old[(size_t)b * KMIX + tid] + expf(sparams[2 * KMIX + tid]);
        salpha[tid] = expf(sparams[tid]);
        sbeta[tid]  = expf(sparams[KMIX + tid]);
        skappa[tid] = kap;
        out_kappa[(size_t)b * KMIX + tid] = kap;
    }
    __syncthreads();

    // ---- Phase 3: phi[t] = sum_k alpha_k * exp(-beta_k * (kappa_k - t)^2) ----
    if (tid < TLEN) {
        const float u = (float)tid;
        float s = 0.0f;
        #pragma unroll
        for (int k = 0; k < KMIX; k++) {
            float d = skappa[k] - u;
            s += salpha[k] * expf(-sbeta[k] * d * d);
        }
        sphi[tid] = s;
    }
    __syncthreads();

    // ---- Phase 4: weight[v] = sum_t phi[t] * onehots[b, t, v] ----
    // 4 groups of 80 threads; group g handles t = g, g+4, ... (interleaved
    // so each iteration the block touches 4 consecutive 320B rows -> coalesced)
    const int g = tid / VDIM;        // 0..3
    const int v = tid - g * VDIM;    // 0..79
    const float* oh = onehots + (size_t)b * TLEN * VDIM;
    float acc = 0.0f;
    #pragma unroll 8
    for (int t = g; t < TLEN; t += 4) {
        acc += sphi[t] * oh[t * VDIM + v];
    }
    wpart[g * VDIM + v] = acc;
    __syncthreads();

    if (tid < VDIM) {
        out_weight[(size_t)b * VDIM + tid] =
            wpart[tid] + wpart[VDIM + tid] + wpart[2 * VDIM + tid] + wpart[3 * VDIM + tid];
    }
}

extern "C" void kernel_launch(void* const* d_in, const int* in_sizes, int n_in,
                              void* d_out, int out_size)
{
    const float* x         = (const float*)d_in[0];   // [B, CELL]
    const float* kappa_old = (const float*)d_in[1];   // [B, K]
    const float* onehots   = (const float*)d_in[2];   // [B, T, V]
    const float* W         = (const float*)d_in[3];   // [3K, CELL]
    const float* bias      = (const float*)d_in[4];   // [3K]
    // d_in[5] = text_len (compile-time constant TLEN=256)

    float* out_weight = (float*)d_out;                        // [B, V]
    float* out_kappa  = (float*)d_out + (size_t)BATCH * VDIM; // [B, K]

    window_kernel<<<BATCH, NTHREADS>>>(x, kappa_old, onehots, W, bias,
                                       out_weight, out_kappa);
}